// round 15
// baseline (speedup 1.0000x reference)
#include <cuda_runtime.h>
#include <math.h>

#define B      64
#define T      200
#define Q      4096
#define Q2     (2*Q)
#define TM1    (T-1)            // 199
#define NROW   (B*TM1)          // 12736
#define NPROBE 12               // probe rows s = 16, 32, ..., 192
#define NPB    (B*NPROBE)       // 768 probe blocks
#define NBLK   (NPB + NROW)     // 13504 blocks, single launch

#define FIX1   268435456.0      // 2^28: per-batch bce sum scale
#define FIX2   1099511627776.0  // 2^40: loss scale

// Scratch (no device allocation allowed)
__device__ unsigned            g_pb[B];    // bits 0..11 probe-done, 16..27 probe-valid
__device__ unsigned long long  g_acc[B];   // [done:8 | flagged:8 | sum_fix:48]
__device__ unsigned long long  g_total;    // [batches:8 | loss_fix:56]
__device__ unsigned long long  g_row[NROW];// general path: [a:1|fl:1|p_bits:32]

__device__ __forceinline__ int check4(float4 v, int vi, int f)
{
    if (v.x != 0.0f) f = vi * 4 + 0;
    if (v.y != 0.0f) f = vi * 4 + 1;
    if (v.z != 0.0f) f = vi * 4 + 2;
    if (v.w != 0.0f) f = vi * 4 + 3;
    return f;
}

// ---------------------------------------------------------------------------
// Row finalization, thread 0 only. Returns (in *fin) whether this block just
// completed its batch and must run the general-path batch epilogue.
//
// Fast path (isTest==0): flags form a prefix => maskf==flag; outputs final
// now. Loss accumulates via ONE relaxed 64-bit L2 atomic per row whose word
// carries completion + count + fixed-point sum together (payload and sync
// arrive atomically -> no fence). Fixed-point adds are exactly associative
// => deterministic. NO gpu-scope release anywhere (R4/R6: per-block release
// at grid ~13k caps the chip at ~2.2 TB/s).
//
// General path (isTest!=0): publish packed (p,a,fl) via atomicExch (L2), then
// bump the same packed batch counter; the completing block runs the epilogue.
// ---------------------------------------------------------------------------
__device__ __forceinline__ void finish_row(const float* __restrict__ pred,
                                           float* __restrict__ d_out,
                                           int isTest, int b, int t, int j,
                                           int* fin, int* fin_cnt)
{
    float p = 0.0f, a = 0.0f;
    int fl = 0;
    if (j >= 0) {
        const int q = j & (Q - 1);
        a  = (j < Q) ? 1.0f : 0.0f;
        p  = __ldg(pred + ((size_t)b * T + t) * (size_t)Q + q);
        fl = 1;
    }
    const int row = b * TM1 + t;

    if (isTest == 0) {
        d_out[1 + row]            = p;           // p * maskf (p==0 if !fl)
        d_out[1 + NROW + row]     = a;           // a * maskf
        d_out[1 + 2 * NROW + row] = (float)fl;   // maskf

        double bce = 0.0;
        if (fl) {
            const float logp = fmaxf(logf(p), -100.0f);
            const float l1mp = fmaxf(log1pf(-p), -100.0f);
            bce = (double)(-(a * logp + (1.0f - a) * l1mp));
        }
        const unsigned long long contrib =
            (1ULL << 56) | ((unsigned long long)fl << 48) |
            (unsigned long long)__double2ll_rn(bce * FIX1);

        const unsigned long long neu = atomicAdd(&g_acc[b], contrib) + contrib;
        if ((neu >> 56) == (unsigned long long)TM1) {    // completed batch b
            const int    cnt = (int)((neu >> 48) & 0xFFULL);
            const double sum = (double)(long long)(neu & 0xFFFFFFFFFFFFULL) / FIX1;
            const double lossb = (cnt > 0) ? (sum / (double)cnt) : 0.0;
            const unsigned long long c2 =
                (1ULL << 56) |
                (unsigned long long)__double2ll_rn(lossb * FIX2);
            const unsigned long long tot = atomicAdd(&g_total, c2) + c2;
            if ((tot >> 56) == (unsigned long long)B) {  // last batch overall
                d_out[0] = (float)((double)(long long)
                                   (tot & 0x00FFFFFFFFFFFFFFULL) / FIX2);
                for (int i = 0; i < B; ++i) { g_pb[i] = 0u; g_acc[i] = 0ULL; }
                g_total = 0ULL;                          // reset for replay
            }
        }
        *fin = 0;
    } else {
        const unsigned long long w =
            ((unsigned long long)(a > 0.0f ? 1u : 0u) << 33) |
            ((unsigned long long)fl << 32) |
            (unsigned long long)__float_as_uint(p);
        atomicExch(&g_row[row], w);              // L2-point publish
        const unsigned long long contrib =
            (1ULL << 56) | ((unsigned long long)fl << 48);
        const unsigned long long neu = atomicAdd(&g_acc[b], contrib) + contrib;
        if ((neu >> 56) == (unsigned long long)TM1) {
            *fin = 1;
            *fin_cnt = (int)((neu >> 48) & 0xFFULL);
        } else {
            *fin = 0;
        }
    }
}

// ---------------------------------------------------------------------------
// General-path batch epilogue (isTest!=0), run by the completing block.
// last = cnt-1 (flags are a prefix). Deterministic shared-tree bce reduce.
// ---------------------------------------------------------------------------
__device__ void general_epi(int b, int cnt, int tsl, float* __restrict__ d_out)
{
    const int tid  = threadIdx.x;
    const int last = max(cnt - 1, 0);
    const int length = last + 1;
    const int start  = (length > tsl) ? (length - tsl) : 0;
    const float fcnt = (float)(last - start + 1);

    float bce = 0.0f;
    if (tid < TM1) {
        const int idx = b * TM1 + tid;
        unsigned long long w;
        asm volatile("ld.global.cg.u64 %0, [%1];" : "=l"(w) : "l"(&g_row[idx]));
        const float p  = __uint_as_float((unsigned)(w & 0xFFFFFFFFULL));
        const float a  = (float)((w >> 33) & 1ULL);
        const bool  m  = (tid >= start) && (tid <= last);
        const float maskf = m ? 1.0f : 0.0f;
        const float logp = fmaxf(logf(p), -100.0f);
        const float l1mp = fmaxf(log1pf(-p), -100.0f);
        bce = -(a * logp + (1.0f - a) * l1mp) * maskf;

        d_out[1 + idx]            = p * maskf;
        d_out[1 + NROW + idx]     = a * maskf;
        d_out[1 + 2 * NROW + idx] = maskf;
    }

    __shared__ float s_f[256];
    s_f[tid] = bce;
    __syncthreads();
    #pragma unroll
    for (int off = 128; off > 0; off >>= 1) {
        if (tid < off) s_f[tid] += s_f[tid + off];
        __syncthreads();
    }

    if (tid == 0) {
        const double lossb = (double)s_f[0] / (double)fcnt;
        const unsigned long long c2 =
            (1ULL << 56) | (unsigned long long)__double2ll_rn(lossb * FIX2);
        const unsigned long long tot = atomicAdd(&g_total, c2) + c2;
        if ((tot >> 56) == (unsigned long long)B) {
            d_out[0] = (float)((double)(long long)
                               (tot & 0x00FFFFFFFFFFFFFFULL) / FIX2);
            for (int i = 0; i < B; ++i) { g_pb[i] = 0u; g_acc[i] = 0ULL; }
            g_total = 0ULL;
        }
    }
}

// ---------------------------------------------------------------------------
// Four-stage row scan: 8 KB per stage. E[bytes] = 20 KB for a uniform one-hot.
// ---------------------------------------------------------------------------
__device__ __forceinline__ int scan_row4(const float* __restrict__ batch,
                                         int b, int s)
{
    const float4* __restrict__ base =
        reinterpret_cast<const float4*>(batch + ((size_t)b * T + s) * (size_t)Q2);
    const int tid = threadIdx.x;

    __shared__ int s_idx;
    if (tid == 0) s_idx = -1;
    __syncthreads();

    #pragma unroll
    for (int st = 0; st < 4; ++st) {
        const int o0 = st * 512 + tid;
        const int o1 = o0 + 256;
        float4 v0 = base[o0];
        float4 v1 = base[o1];
        int f = -1;
        f = check4(v0, o0, f);
        f = check4(v1, o1, f);
        if (f >= 0) s_idx = f;
        if (st < 3) {
            if (__syncthreads_or(f >= 0)) return s_idx;
        } else {
            __syncthreads();
        }
    }
    return s_idx;
}

// ---------------------------------------------------------------------------
// Single fused kernel: bids [0,768) probe; bids [768, NBLK) scan (t-major).
// Publish = plain atomicOr (L2-point); poll = ld.global.cg, bounded spin +
// full-scan fallback (deadlock-free). Loss finishes in-kernel both paths.
// ---------------------------------------------------------------------------
__global__ __launch_bounds__(256)
void fused_kernel(const float* __restrict__ pred,
                  const float* __restrict__ batch,
                  const int*   __restrict__ isTestP,
                  const int*   __restrict__ tslP,
                  float*       __restrict__ d_out)
{
    const int bid    = blockIdx.x;
    const int tid    = threadIdx.x;
    const int isTest = __ldg(isTestP);

    __shared__ int s_fin, s_cnt;
    if (tid == 0) s_fin = 0;

    int b, t, j;

    if (bid < NPB) {
        // ---- probe block: full row, MLP=8, one barrier ----
        b = bid / NPROBE;
        const int k = bid % NPROBE;
        const int s = 16 * (k + 1);
        t = s - 1;
        const float4* __restrict__ base =
            reinterpret_cast<const float4*>(batch + ((size_t)b * T + s) * (size_t)Q2);

        __shared__ int s_idx;
        if (tid == 0) s_idx = -1;
        __syncthreads();

        float4 v[8];
        #pragma unroll
        for (int c = 0; c < 8; ++c) v[c] = base[c * 256 + tid];
        int f = -1;
        #pragma unroll
        for (int c = 0; c < 8; ++c) f = check4(v[c], c * 256 + tid, f);
        if (f >= 0) s_idx = f;
        __syncthreads();
        j = s_idx;

        if (tid == 0) {
            const unsigned bits =
                (1u << k) | ((j >= 0) ? (1u << (16 + k)) : 0u);
            atomicOr(&g_pb[b], bits);            // plain L2 publish, no fence
        }
    } else {
        // ---- scan block (t-major) ----
        const int sb = bid - NPB;
        t = sb / B;
        b = sb % B;
        const int s = t + 1;
        if (s <= 192 && (s & 15) == 0) return;   // handled by a probe block

        // Partial-info wait: only probes k with 16(k+1) <= s govern this row.
        const int kmax = min(s >> 4, NPROBE);
        unsigned v = 0;
        if (kmax > 0) {
            const unsigned need = (1u << kmax) - 1u;
            __shared__ unsigned s_v;
            if (tid == 0) {
                unsigned w = 0;
                int it = 0;
                do {
                    asm volatile("ld.global.cg.u32 %0, [%1];"
                                 : "=r"(w) : "l"(&g_pb[b]) : "memory");
                    if ((w & need) == need) break;
                    __nanosleep(64);
                } while (++it < 20000);
                s_v = ((w & need) == need) ? w : 0u;  // timeout => no info
            }
            __syncthreads();
            v = s_v;
        }

        int ub = 200;
        #pragma unroll
        for (int k = NPROBE - 1; k >= 0; --k)
            if (((v >> k) & 1u) && !((v >> (16 + k)) & 1u)) ub = 16 * (k + 1);

        if (s >= ub) {
            j = -1;                              // provably all-zero: no reads
        } else {
            j = scan_row4(batch, b, s);
        }
    }

    // ---- row finalization + possible in-kernel batch epilogue ----
    if (tid == 0) {
        int fin = 0, fcnt = 0;
        finish_row(pred, d_out, isTest, b, t, j, &fin, &fcnt);
        s_fin = fin;
        s_cnt = fcnt;
    }
    __syncthreads();
    if (s_fin) {                                 // general path only
        general_epi(b, s_cnt, __ldg(tslP), d_out);
    }
}

extern "C" void kernel_launch(void* const* d_in, const int* in_sizes, int n_in,
                              void* d_out, int out_size)
{
    const float* pred  = (const float*)d_in[0];
    const float* batch = (const float*)d_in[1];
    const int*   isT   = (const int*)d_in[2];
    const int*   tsl   = (const int*)d_in[3];
    float*       out   = (float*)d_out;

    fused_kernel<<<NBLK, 256>>>(pred, batch, isT, tsl, out);
}

// round 16
// speedup vs baseline: 1.0537x; 1.0537x over previous
#include <cuda_runtime.h>
#include <math.h>

#define B      64
#define T      200
#define Q      4096
#define Q2     (2*Q)
#define TM1    (T-1)            // 199
#define NROW   (B*TM1)          // 12736
#define NPROBE 12               // probe rows s = 16, 32, ..., 192
#define NPB    (B*NPROBE)       // 768 probe blocks
#define NBLK   (NPB + NROW)     // 13504 blocks, single launch

#define FIX1   268435456.0      // 2^28: per-batch bce sum scale
#define FIX2   1099511627776.0  // 2^40: loss scale

// Scratch (no device allocation allowed)
__device__ unsigned            g_pb[B];    // bits 0..11 probe-done, 16..27 probe-valid
__device__ unsigned long long  g_acc[B];   // [done:8 | flagged:8 | sum_fix:48]
__device__ unsigned long long  g_total;    // [batches:8 | loss_fix:56]
__device__ unsigned long long  g_row[NROW];// general path: [a:1|fl:1|p_bits:32]

__device__ __forceinline__ int check4(float4 v, int vi, int f)
{
    if (v.x != 0.0f) f = vi * 4 + 0;
    if (v.y != 0.0f) f = vi * 4 + 1;
    if (v.z != 0.0f) f = vi * 4 + 2;
    if (v.w != 0.0f) f = vi * 4 + 3;
    return f;
}

// ---------------------------------------------------------------------------
// FAST-PATH row finalization (isTest==0), called by thread 0 ONLY while the
// other 255 threads have already exited (no trailing barrier — the R15
// regression was pinning 8 warps per block on this chain). Flags form a
// prefix => maskf==flag; outputs are final now. Loss accumulates via ONE
// relaxed 64-bit L2 atomic per row whose word carries completion + count +
// fixed-point sum together (payload and sync arrive atomically -> no fence;
// fixed-point adds are exactly associative => deterministic). NO gpu-scope
// release anywhere (R4/R6: per-block release at grid ~13k caps the chip).
// ---------------------------------------------------------------------------
__device__ __forceinline__ void finish_row_fast(const float* __restrict__ pred,
                                                float* __restrict__ d_out,
                                                int b, int t, int j)
{
    float p = 0.0f, a = 0.0f;
    int fl = 0;
    if (j >= 0) {
        const int q = j & (Q - 1);
        a  = (j < Q) ? 1.0f : 0.0f;
        p  = __ldg(pred + ((size_t)b * T + t) * (size_t)Q + q);
        fl = 1;
    }
    const int row = b * TM1 + t;

    d_out[1 + row]            = p;           // p * maskf (p==0 if !fl)
    d_out[1 + NROW + row]     = a;           // a * maskf
    d_out[1 + 2 * NROW + row] = (float)fl;   // maskf

    double bce = 0.0;
    if (fl) {
        const float logp = fmaxf(logf(p), -100.0f);
        const float l1mp = fmaxf(log1pf(-p), -100.0f);
        bce = (double)(-(a * logp + (1.0f - a) * l1mp));
    }
    const unsigned long long contrib =
        (1ULL << 56) | ((unsigned long long)fl << 48) |
        (unsigned long long)__double2ll_rn(bce * FIX1);

    const unsigned long long neu = atomicAdd(&g_acc[b], contrib) + contrib;
    if ((neu >> 56) == (unsigned long long)TM1) {        // completed batch b
        const int    cnt = (int)((neu >> 48) & 0xFFULL);
        const double sum = (double)(long long)(neu & 0xFFFFFFFFFFFFULL) / FIX1;
        const double lossb = (cnt > 0) ? (sum / (double)cnt) : 0.0;
        const unsigned long long c2 =
            (1ULL << 56) | (unsigned long long)__double2ll_rn(lossb * FIX2);
        const unsigned long long tot = atomicAdd(&g_total, c2) + c2;
        if ((tot >> 56) == (unsigned long long)B) {      // last batch overall
            d_out[0] = (float)((double)(long long)
                               (tot & 0x00FFFFFFFFFFFFFFULL) / FIX2);
            for (int i = 0; i < B; ++i) { g_pb[i] = 0u; g_acc[i] = 0ULL; }
            g_total = 0ULL;                              // reset for replay
        }
    }
}

// ---------------------------------------------------------------------------
// General-path batch epilogue (isTest!=0), run by the completing block.
// ---------------------------------------------------------------------------
__device__ void general_epi(int b, int cnt, int tsl, float* __restrict__ d_out)
{
    const int tid  = threadIdx.x;
    const int last = max(cnt - 1, 0);
    const int length = last + 1;
    const int start  = (length > tsl) ? (length - tsl) : 0;
    const float fcnt = (float)(last - start + 1);

    float bce = 0.0f;
    if (tid < TM1) {
        const int idx = b * TM1 + tid;
        unsigned long long w;
        asm volatile("ld.global.cg.u64 %0, [%1];" : "=l"(w) : "l"(&g_row[idx]));
        const float p  = __uint_as_float((unsigned)(w & 0xFFFFFFFFULL));
        const float a  = (float)((w >> 33) & 1ULL);
        const bool  m  = (tid >= start) && (tid <= last);
        const float maskf = m ? 1.0f : 0.0f;
        const float logp = fmaxf(logf(p), -100.0f);
        const float l1mp = fmaxf(log1pf(-p), -100.0f);
        bce = -(a * logp + (1.0f - a) * l1mp) * maskf;

        d_out[1 + idx]            = p * maskf;
        d_out[1 + NROW + idx]     = a * maskf;
        d_out[1 + 2 * NROW + idx] = maskf;
    }

    __shared__ float s_f[256];
    s_f[tid] = bce;
    __syncthreads();
    #pragma unroll
    for (int off = 128; off > 0; off >>= 1) {
        if (tid < off) s_f[tid] += s_f[tid + off];
        __syncthreads();
    }

    if (tid == 0) {
        const double lossb = (double)s_f[0] / (double)fcnt;
        const unsigned long long c2 =
            (1ULL << 56) | (unsigned long long)__double2ll_rn(lossb * FIX2);
        const unsigned long long tot = atomicAdd(&g_total, c2) + c2;
        if ((tot >> 56) == (unsigned long long)B) {
            d_out[0] = (float)((double)(long long)
                               (tot & 0x00FFFFFFFFFFFFFFULL) / FIX2);
            for (int i = 0; i < B; ++i) { g_pb[i] = 0u; g_acc[i] = 0ULL; }
            g_total = 0ULL;
        }
    }
}

// ---------------------------------------------------------------------------
// Four-stage row scan: 8 KB per stage. E[bytes] = 20 KB for a uniform one-hot.
// ---------------------------------------------------------------------------
__device__ __forceinline__ int scan_row4(const float* __restrict__ batch,
                                         int b, int s)
{
    const float4* __restrict__ base =
        reinterpret_cast<const float4*>(batch + ((size_t)b * T + s) * (size_t)Q2);
    const int tid = threadIdx.x;

    __shared__ int s_idx;
    if (tid == 0) s_idx = -1;
    __syncthreads();

    #pragma unroll
    for (int st = 0; st < 4; ++st) {
        const int o0 = st * 512 + tid;
        const int o1 = o0 + 256;
        float4 v0 = base[o0];
        float4 v1 = base[o1];
        int f = -1;
        f = check4(v0, o0, f);
        f = check4(v1, o1, f);
        if (f >= 0) s_idx = f;
        if (st < 3) {
            if (__syncthreads_or(f >= 0)) return s_idx;
        } else {
            __syncthreads();
        }
    }
    return s_idx;
}

// ---------------------------------------------------------------------------
// Single fused kernel: bids [0,768) probe; bids [768, NBLK) scan (t-major).
// Publish = plain atomicOr (L2-point); poll = ld.global.cg, bounded spin +
// full-scan fallback (deadlock-free). Loss finishes in-kernel both paths.
// Fast path has NO barrier after the scan: threads 1..255 exit immediately.
// ---------------------------------------------------------------------------
__global__ __launch_bounds__(256)
void fused_kernel(const float* __restrict__ pred,
                  const float* __restrict__ batch,
                  const int*   __restrict__ isTestP,
                  const int*   __restrict__ tslP,
                  float*       __restrict__ d_out)
{
    const int bid    = blockIdx.x;
    const int tid    = threadIdx.x;
    const int isTest = __ldg(isTestP);

    int b, t, j;

    if (bid < NPB) {
        // ---- probe block: full row, MLP=8, one barrier ----
        b = bid / NPROBE;
        const int k = bid % NPROBE;
        const int s = 16 * (k + 1);
        t = s - 1;
        const float4* __restrict__ base =
            reinterpret_cast<const float4*>(batch + ((size_t)b * T + s) * (size_t)Q2);

        __shared__ int s_idx;
        if (tid == 0) s_idx = -1;
        __syncthreads();

        float4 v[8];
        #pragma unroll
        for (int c = 0; c < 8; ++c) v[c] = base[c * 256 + tid];
        int f = -1;
        #pragma unroll
        for (int c = 0; c < 8; ++c) f = check4(v[c], c * 256 + tid, f);
        if (f >= 0) s_idx = f;
        __syncthreads();
        j = s_idx;

        if (tid == 0) {
            const unsigned bits =
                (1u << k) | ((j >= 0) ? (1u << (16 + k)) : 0u);
            atomicOr(&g_pb[b], bits);            // plain L2 publish, no fence
        }
    } else {
        // ---- scan block (t-major) ----
        const int sb = bid - NPB;
        t = sb / B;
        b = sb % B;
        const int s = t + 1;
        if (s <= 192 && (s & 15) == 0) return;   // handled by a probe block

        // Partial-info wait: only probes k with 16(k+1) <= s govern this row.
        const int kmax = min(s >> 4, NPROBE);
        unsigned v = 0;
        if (kmax > 0) {
            const unsigned need = (1u << kmax) - 1u;
            __shared__ unsigned s_v;
            if (tid == 0) {
                unsigned w = 0;
                int it = 0;
                do {
                    asm volatile("ld.global.cg.u32 %0, [%1];"
                                 : "=r"(w) : "l"(&g_pb[b]) : "memory");
                    if ((w & need) == need) break;
                    __nanosleep(64);
                } while (++it < 20000);
                s_v = ((w & need) == need) ? w : 0u;  // timeout => no info
            }
            __syncthreads();
            v = s_v;
        }

        int ub = 200;
        #pragma unroll
        for (int k = NPROBE - 1; k >= 0; --k)
            if (((v >> k) & 1u) && !((v >> (16 + k)) & 1u)) ub = 16 * (k + 1);

        if (s >= ub) {
            j = -1;                              // provably all-zero: no reads
        } else {
            j = scan_row4(batch, b, s);
        }
    }

    if (isTest == 0) {
        // FAST PATH: thread 0 finalizes alone; everyone else exits NOW.
        if (tid == 0) finish_row_fast(pred, d_out, b, t, j);
        return;
    }

    // ---- general path (isTest != 0): barrier is acceptable here ----
    __shared__ int s_fin, s_cnt;
    if (tid == 0) {
        float p = 0.0f, a = 0.0f;
        int fl = 0;
        if (j >= 0) {
            const int q = j & (Q - 1);
            a  = (j < Q) ? 1.0f : 0.0f;
            p  = __ldg(pred + ((size_t)b * T + t) * (size_t)Q + q);
            fl = 1;
        }
        const int row = b * TM1 + t;
        const unsigned long long w =
            ((unsigned long long)(a > 0.0f ? 1u : 0u) << 33) |
            ((unsigned long long)fl << 32) |
            (unsigned long long)__float_as_uint(p);
        atomicExch(&g_row[row], w);              // L2-point publish
        const unsigned long long contrib =
            (1ULL << 56) | ((unsigned long long)fl << 48);
        const unsigned long long neu = atomicAdd(&g_acc[b], contrib) + contrib;
        s_fin = ((neu >> 56) == (unsigned long long)TM1) ? 1 : 0;
        s_cnt = (int)((neu >> 48) & 0xFFULL);
    }
    __syncthreads();
    if (s_fin) general_epi(b, s_cnt, __ldg(tslP), d_out);
}

extern "C" void kernel_launch(void* const* d_in, const int* in_sizes, int n_in,
                              void* d_out, int out_size)
{
    const float* pred  = (const float*)d_in[0];
    const float* batch = (const float*)d_in[1];
    const int*   isT   = (const int*)d_in[2];
    const int*   tsl   = (const int*)d_in[3];
    float*       out   = (float*)d_out;

    fused_kernel<<<NBLK, 256>>>(pred, batch, isT, tsl, out);
}

// round 17
// speedup vs baseline: 1.1096x; 1.0531x over previous
#include <cuda_runtime.h>
#include <math.h>

#define B      64
#define T      200
#define Q      4096
#define Q2     (2*Q)
#define TM1    (T-1)            // 199
#define NROW   (B*TM1)          // 12736
#define NPROBE 12               // probe rows s = 16, 32, ..., 192
#define NPB    (B*NPROBE)       // 768 probe blocks
#define NBLK   (1 + NPB + NROW) // poller + probes + scans, single launch

#define FIX1   268435456.0      // 2^28: per-batch bce sum scale
#define FIX2   1099511627776.0  // 2^40: loss scale

// Scratch (no device allocation allowed)
__device__ unsigned            g_pb[B];    // bits 0..11 probe-done, 16..27 probe-valid
__device__ unsigned long long  g_acc[B];   // [done:8 | flagged:8 | sum_fix:48]
__device__ unsigned long long  g_total;    // general path only
__device__ unsigned long long  g_row[NROW];// general path: [a:1|fl:1|p_bits:32]

__device__ __forceinline__ int check4(float4 v, int vi, int f)
{
    if (v.x != 0.0f) f = vi * 4 + 0;
    if (v.y != 0.0f) f = vi * 4 + 1;
    if (v.z != 0.0f) f = vi * 4 + 2;
    if (v.w != 0.0f) f = vi * 4 + 3;
    return f;
}

// ---------------------------------------------------------------------------
// FAST-PATH row finalization (isTest==0), thread 0 only, FIRE-AND-FORGET:
// red.global.add.u64 has no return value, so thread 0 never waits on the L2
// round trip (the R16 occupancy killer: return-value ATOMG added ~320 cyc to
// every block's retirement). Completion + count + fixed-point sum travel in
// ONE word => no fence needed (R4/R6 invariant: no gpu-scope release at
// grid ~13k). Fixed-point adds are exactly associative => deterministic.
// ---------------------------------------------------------------------------
__device__ __forceinline__ void finish_row_fast(const float* __restrict__ pred,
                                                float* __restrict__ d_out,
                                                int b, int t, int j)
{
    float p = 0.0f, a = 0.0f;
    int fl = 0;
    if (j >= 0) {
        const int q = j & (Q - 1);
        a  = (j < Q) ? 1.0f : 0.0f;
        p  = __ldg(pred + ((size_t)b * T + t) * (size_t)Q + q);
        fl = 1;
    }
    const int row = b * TM1 + t;

    d_out[1 + row]            = p;           // p * maskf (p==0 if !fl)
    d_out[1 + NROW + row]     = a;           // a * maskf
    d_out[1 + 2 * NROW + row] = (float)fl;   // maskf

    double bce = 0.0;
    if (fl) {
        const float logp = fmaxf(logf(p), -100.0f);
        const float l1mp = fmaxf(log1pf(-p), -100.0f);
        bce = (double)(-(a * logp + (1.0f - a) * l1mp));
    }
    const unsigned long long contrib =
        (1ULL << 56) | ((unsigned long long)fl << 48) |
        (unsigned long long)__double2ll_rn(bce * FIX1);

    asm volatile("red.global.add.u64 [%0], %1;"
                 :: "l"(&g_acc[b]), "l"(contrib) : "memory");
}

// ---------------------------------------------------------------------------
// Poller block (bid 0, fast path only): lanes 0..63 spin on their batch's
// g_acc word (ld.cg = L2-coherent with RED) until done==199, then fold the
// loss in fixed point (deterministic tree) and reset state for graph replay.
// Bounded spin (generous) so a bug can't hang the bench.
// ---------------------------------------------------------------------------
__device__ void poller_fast(float* __restrict__ d_out)
{
    const int tid = threadIdx.x;

    long long c2 = 0;
    if (tid < B) {
        unsigned long long w = 0;
        int it = 0;
        do {
            asm volatile("ld.global.cg.u64 %0, [%1];"
                         : "=l"(w) : "l"(&g_acc[tid]) : "memory");
            if ((w >> 56) == (unsigned long long)TM1) break;
            __nanosleep(256);
        } while (++it < 2000000);

        const int    cnt = (int)((w >> 48) & 0xFFULL);
        const double sum = (double)(long long)(w & 0xFFFFFFFFFFFFULL) / FIX1;
        const double lossb = (cnt > 0) ? (sum / (double)cnt) : 0.0;
        c2 = __double2ll_rn(lossb * FIX2);

        g_acc[tid] = 0ULL;                   // reset for next replay
        g_pb[tid]  = 0u;
    }

    __shared__ long long s2[64];
    if (tid < 64) s2[tid] = c2;
    __syncthreads();
    #pragma unroll
    for (int off = 32; off > 0; off >>= 1) {
        if (tid < off) s2[tid] += s2[tid + off];
        __syncthreads();
    }
    if (tid == 0) d_out[0] = (float)((double)s2[0] / FIX2);
}

// ---------------------------------------------------------------------------
// General-path batch epilogue (isTest!=0, unbenchmarked), run by the
// completing block (return-value atomics acceptable off the fast path).
// ---------------------------------------------------------------------------
__device__ void general_epi(int b, int cnt, int tsl, float* __restrict__ d_out)
{
    const int tid  = threadIdx.x;
    const int last = max(cnt - 1, 0);
    const int length = last + 1;
    const int start  = (length > tsl) ? (length - tsl) : 0;
    const float fcnt = (float)(last - start + 1);

    float bce = 0.0f;
    if (tid < TM1) {
        const int idx = b * TM1 + tid;
        unsigned long long w;
        asm volatile("ld.global.cg.u64 %0, [%1];" : "=l"(w) : "l"(&g_row[idx]));
        const float p  = __uint_as_float((unsigned)(w & 0xFFFFFFFFULL));
        const float a  = (float)((w >> 33) & 1ULL);
        const bool  m  = (tid >= start) && (tid <= last);
        const float maskf = m ? 1.0f : 0.0f;
        const float logp = fmaxf(logf(p), -100.0f);
        const float l1mp = fmaxf(log1pf(-p), -100.0f);
        bce = -(a * logp + (1.0f - a) * l1mp) * maskf;

        d_out[1 + idx]            = p * maskf;
        d_out[1 + NROW + idx]     = a * maskf;
        d_out[1 + 2 * NROW + idx] = maskf;
    }

    __shared__ float s_f[256];
    s_f[tid] = bce;
    __syncthreads();
    #pragma unroll
    for (int off = 128; off > 0; off >>= 1) {
        if (tid < off) s_f[tid] += s_f[tid + off];
        __syncthreads();
    }

    if (tid == 0) {
        const double lossb = (double)s_f[0] / (double)fcnt;
        const unsigned long long c2 =
            (1ULL << 56) | (unsigned long long)__double2ll_rn(lossb * FIX2);
        const unsigned long long tot = atomicAdd(&g_total, c2) + c2;
        if ((tot >> 56) == (unsigned long long)B) {
            d_out[0] = (float)((double)(long long)
                               (tot & 0x00FFFFFFFFFFFFFFULL) / FIX2);
            for (int i = 0; i < B; ++i) { g_pb[i] = 0u; g_acc[i] = 0ULL; }
            g_total = 0ULL;
        }
    }
}

// ---------------------------------------------------------------------------
// Four-stage row scan: 8 KB per stage. E[bytes] = 20 KB for a uniform one-hot.
// ---------------------------------------------------------------------------
__device__ __forceinline__ int scan_row4(const float* __restrict__ batch,
                                         int b, int s)
{
    const float4* __restrict__ base =
        reinterpret_cast<const float4*>(batch + ((size_t)b * T + s) * (size_t)Q2);
    const int tid = threadIdx.x;

    __shared__ int s_idx;
    if (tid == 0) s_idx = -1;
    __syncthreads();

    #pragma unroll
    for (int st = 0; st < 4; ++st) {
        const int o0 = st * 512 + tid;
        const int o1 = o0 + 256;
        float4 v0 = base[o0];
        float4 v1 = base[o1];
        int f = -1;
        f = check4(v0, o0, f);
        f = check4(v1, o1, f);
        if (f >= 0) s_idx = f;
        if (st < 3) {
            if (__syncthreads_or(f >= 0)) return s_idx;
        } else {
            __syncthreads();
        }
    }
    return s_idx;
}

// ---------------------------------------------------------------------------
// Single fused kernel. bid 0: poller (fast path). bids [1, 1+NPB): probes.
// bids [1+NPB, NBLK): scans (t-major). Publish = plain atomicOr (L2-point);
// poll = ld.global.cg, bounded spin + full-scan fallback. Fast path rows are
// fire-and-forget; threads 1..255 exit right after the scan.
// ---------------------------------------------------------------------------
__global__ __launch_bounds__(256)
void fused_kernel(const float* __restrict__ pred,
                  const float* __restrict__ batch,
                  const int*   __restrict__ isTestP,
                  const int*   __restrict__ tslP,
                  float*       __restrict__ d_out)
{
    const int bid    = blockIdx.x;
    const int tid    = threadIdx.x;
    const int isTest = __ldg(isTestP);

    if (bid == 0) {                              // ---- poller block ----
        if (isTest == 0) poller_fast(d_out);     // general path finishes itself
        return;
    }

    int b, t, j;

    if (bid <= NPB) {
        // ---- probe block: full row, MLP=8, one barrier ----
        const int idx = bid - 1;
        b = idx / NPROBE;
        const int k = idx % NPROBE;
        const int s = 16 * (k + 1);
        t = s - 1;
        const float4* __restrict__ base =
            reinterpret_cast<const float4*>(batch + ((size_t)b * T + s) * (size_t)Q2);

        __shared__ int s_idx;
        if (tid == 0) s_idx = -1;
        __syncthreads();

        float4 v[8];
        #pragma unroll
        for (int c = 0; c < 8; ++c) v[c] = base[c * 256 + tid];
        int f = -1;
        #pragma unroll
        for (int c = 0; c < 8; ++c) f = check4(v[c], c * 256 + tid, f);
        if (f >= 0) s_idx = f;
        __syncthreads();
        j = s_idx;

        if (tid == 0) {
            const unsigned bits =
                (1u << k) | ((j >= 0) ? (1u << (16 + k)) : 0u);
            atomicOr(&g_pb[b], bits);            // plain L2 publish, no fence
        }
    } else {
        // ---- scan block (t-major) ----
        const int sb = bid - 1 - NPB;
        t = sb / B;
        b = sb % B;
        const int s = t + 1;
        if (s <= 192 && (s & 15) == 0) return;   // handled by a probe block

        // Partial-info wait: only probes k with 16(k+1) <= s govern this row.
        const int kmax = min(s >> 4, NPROBE);
        unsigned v = 0;
        if (kmax > 0) {
            const unsigned need = (1u << kmax) - 1u;
            __shared__ unsigned s_v;
            if (tid == 0) {
                unsigned w = 0;
                int it = 0;
                do {
                    asm volatile("ld.global.cg.u32 %0, [%1];"
                                 : "=r"(w) : "l"(&g_pb[b]) : "memory");
                    if ((w & need) == need) break;
                    __nanosleep(64);
                } while (++it < 20000);
                s_v = ((w & need) == need) ? w : 0u;  // timeout => no info
            }
            __syncthreads();
            v = s_v;
        }

        int ub = 200;
        #pragma unroll
        for (int k = NPROBE - 1; k >= 0; --k)
            if (((v >> k) & 1u) && !((v >> (16 + k)) & 1u)) ub = 16 * (k + 1);

        if (s >= ub) {
            j = -1;                              // provably all-zero: no reads
        } else {
            j = scan_row4(batch, b, s);
        }
    }

    if (isTest == 0) {
        // FAST PATH: thread 0 fires and forgets; everyone else exits NOW.
        if (tid == 0) finish_row_fast(pred, d_out, b, t, j);
        return;
    }

    // ---- general path (isTest != 0) ----
    __shared__ int s_fin, s_cnt;
    if (tid == 0) {
        float p = 0.0f, a = 0.0f;
        int fl = 0;
        if (j >= 0) {
            const int q = j & (Q - 1);
            a  = (j < Q) ? 1.0f : 0.0f;
            p  = __ldg(pred + ((size_t)b * T + t) * (size_t)Q + q);
            fl = 1;
        }
        const int row = b * TM1 + t;
        const unsigned long long w =
            ((unsigned long long)(a > 0.0f ? 1u : 0u) << 33) |
            ((unsigned long long)fl << 32) |
            (unsigned long long)__float_as_uint(p);
        atomicExch(&g_row[row], w);              // L2-point publish
        const unsigned long long contrib =
            (1ULL << 56) | ((unsigned long long)fl << 48);
        const unsigned long long neu = atomicAdd(&g_acc[b], contrib) + contrib;
        s_fin = ((neu >> 56) == (unsigned long long)TM1) ? 1 : 0;
        s_cnt = (int)((neu >> 48) & 0xFFULL);
    }
    __syncthreads();
    if (s_fin) general_epi(b, s_cnt, __ldg(tslP), d_out);
}

extern "C" void kernel_launch(void* const* d_in, const int* in_sizes, int n_in,
                              void* d_out, int out_size)
{
    const float* pred  = (const float*)d_in[0];
    const float* batch = (const float*)d_in[1];
    const int*   isT   = (const int*)d_in[2];
    const int*   tsl   = (const int*)d_in[3];
    float*       out   = (float*)d_out;

    fused_kernel<<<NBLK, 256>>>(pred, batch, isT, tsl, out);
}